// round 2
// baseline (speedup 1.0000x reference)
#include <cuda_runtime.h>

// Depthwise causal FIR conv1d, K=31, fp32.
// x: (B=8, L=4096, C=2048) channel-last.  w: (C, 31).  y like x.
//
// Round-2 design: thread = channel PAIR (2c,2c+1) as float2 + 16 l-positions.
// All math via fma.rn.f32x2 (FFMA2) -> half the fma-pipe issue of scalar FFMA,
// bit-exact fp32. Window front-batched in registers (MLP=46).

#define BB 8
#define LL 4096
#define CC 2048
#define KK 31
#define TT 16           // l-positions per thread
#define THREADS 128     // channel-pairs per block

__device__ __forceinline__ float2 ffma2(float2 a, float2 b, float2 c) {
    float2 d;
    asm("fma.rn.f32x2 %0, %1, %2, %3;"
        : "=l"(*reinterpret_cast<unsigned long long*>(&d))
        : "l"(*reinterpret_cast<const unsigned long long*>(&a)),
          "l"(*reinterpret_cast<const unsigned long long*>(&b)),
          "l"(*reinterpret_cast<const unsigned long long*>(&c)));
    return d;
}

__global__ __launch_bounds__(THREADS, 1)
void _DepthwiseFIRConv1d_kernel(const float* __restrict__ x,
                                const float* __restrict__ w,
                                float* __restrict__ y) {
    const int cp = blockIdx.x * THREADS + threadIdx.x;   // channel pair 0..1023
    const int c0 = cp * 2;
    const int l0 = blockIdx.y * TT;
    const int b  = blockIdx.z;

    const float2* xb = reinterpret_cast<const float2*>(x + (size_t)(b * LL) * CC) + cp;
    const int base = l0 - (KK - 1);

    // Front-batched window: 46 independent LDG.64 -> deep MLP.
    float2 xv[TT + KK - 1];
#pragma unroll
    for (int i = 0; i < TT + KK - 1; i++) {
        const int l = base + i;
        xv[i] = (l >= 0) ? xb[(size_t)l * (CC / 2)] : make_float2(0.0f, 0.0f);
    }

    float2 acc[TT];
#pragma unroll
    for (int j = 0; j < TT; j++) acc[j] = make_float2(0.0f, 0.0f);

    const float* wc0 = w + c0 * KK;        // taps for channel c0
    const float* wc1 = wc0 + KK;           // taps for channel c0+1
#pragma unroll
    for (int t = 0; t < KK; t++) {
        const float2 wt = make_float2(__ldg(wc0 + t), __ldg(wc1 + t));
#pragma unroll
        for (int j = 0; j < TT; j++) {
            acc[j] = ffma2(wt, xv[t + j], acc[j]);       // 2 fp32 FMAs / issue
        }
    }

    float2* yb = reinterpret_cast<float2*>(y + (size_t)(b * LL + l0) * CC) + cp;
#pragma unroll
    for (int j = 0; j < TT; j++) {
        yb[(size_t)j * (CC / 2)] = acc[j];
    }
}

extern "C" void kernel_launch(void* const* d_in, const int* in_sizes, int n_in,
                              void* d_out, int out_size) {
    const float* x = (const float*)d_in[0];   // (8, 4096, 16, 128)
    const float* w = (const float*)d_in[1];   // (16, 128, 31)
    float* yv = (float*)d_out;

    dim3 grid((CC / 2) / THREADS, LL / TT, BB);   // (8, 256, 8) = 16384 blocks
    _DepthwiseFIRConv1d_kernel<<<grid, THREADS>>>(x, w, yv);
}

// round 3
// speedup vs baseline: 1.5345x; 1.5345x over previous
#include <cuda_runtime.h>

// Depthwise causal FIR conv1d, K=31, fp32.
// x: (8, 4096, 2048) channel-last.  w: (2048, 31).  y like x.
//
// Round-3: streaming register-window kernel.
//  - thread = channel pair (float2), T=128 consecutive l-outputs
//  - 31 float2 taps held in registers for the whole thread (1 load, 128 reuses)
//  - 46-slot circular float2 window, static mod-46 indexing (full unroll, no MOVs)
//  - 8-output chunks: 124 FFMA2 + 8 prefetch LDG.64 (ready 2 chunks early) + 8 STG.64
//  - halo read amplification (128+30)/128 = 1.23

#define BB 8
#define LL 4096
#define CP 1024          // channel pairs (C=2048)
#define KK 31
#define CHUNK 8
#define TT 128           // outputs per thread
#define NCHUNK (TT / CHUNK)   // 16
#define WBUF 46          // window slots (38 live + 8 prefetch headroom)
#define THREADS 64

__device__ __forceinline__ float2 ffma2(float2 a, float2 b, float2 c) {
    float2 d;
    asm("fma.rn.f32x2 %0, %1, %2, %3;"
        : "=l"(*reinterpret_cast<unsigned long long*>(&d))
        : "l"(*reinterpret_cast<const unsigned long long*>(&a)),
          "l"(*reinterpret_cast<const unsigned long long*>(&b)),
          "l"(*reinterpret_cast<const unsigned long long*>(&c)));
    return d;
}

__global__ __launch_bounds__(THREADS)
void _DepthwiseFIRConv1d_kernel(const float* __restrict__ x,
                                const float* __restrict__ w,
                                float* __restrict__ y) {
    const int cp = blockIdx.x * THREADS + threadIdx.x;   // 0..1023
    const int l0 = blockIdx.y * TT;
    const int b  = blockIdx.z;

    const float2* xb = reinterpret_cast<const float2*>(x) + (size_t)b * LL * CP + cp;
    float2*       yb = reinterpret_cast<float2*>(y) + ((size_t)b * LL + l0) * CP + cp;
    const int base = l0 - (KK - 1);

    // Taps for both channels of the pair -> registers for the whole thread.
    const float* w0 = w + (2 * cp) * KK;
    float2 wt[KK];
#pragma unroll
    for (int t = 0; t < KK; t++)
        wt[t] = make_float2(__ldg(w0 + t), __ldg(w0 + KK + t));

    // Initial window: offsets 0..45 (covers chunks 0 and 1). Only l0==0 predicates.
    float2 buf[WBUF];
#pragma unroll
    for (int i = 0; i < WBUF; i++) {
        const int l = base + i;
        buf[i] = (l >= 0) ? xb[(size_t)l * CP] : make_float2(0.0f, 0.0f);
    }

#pragma unroll
    for (int c = 0; c < NCHUNK; c++) {
        float2 acc[CHUNK];
#pragma unroll
        for (int j = 0; j < CHUNK; j++) acc[j] = make_float2(0.0f, 0.0f);

#pragma unroll
        for (int t = 0; t < KK; t++) {
#pragma unroll
            for (int j = 0; j < CHUNK; j++) {
                // window offset (CHUNK*c + j + t) lives in slot (offset % WBUF)
                acc[j] = ffma2(wt[t], buf[(CHUNK * c + j + t) % WBUF], acc[j]);
            }
        }

#pragma unroll
        for (int j = 0; j < CHUNK; j++)
            yb[(size_t)(CHUNK * c + j) * CP] = acc[j];

        // Prefetch window offsets [46+8c .. 53+8c] (used by chunk c+2).
        // Always in-range: l = base+46+8c+i >= l0+16 >= 0, <= l0+127 < L.
        if (c < NCHUNK - 2) {
#pragma unroll
            for (int i = 0; i < CHUNK; i++) {
                const int off = WBUF + CHUNK * c + i;
                buf[off % WBUF] = xb[(size_t)(base + off) * CP];
            }
        }
    }
}

extern "C" void kernel_launch(void* const* d_in, const int* in_sizes, int n_in,
                              void* d_out, int out_size) {
    const float* x = (const float*)d_in[0];   // (8, 4096, 16, 128)
    const float* w = (const float*)d_in[1];   // (16, 128, 31)
    float* yv = (float*)d_out;

    dim3 grid(CP / THREADS, LL / TT, BB);     // (16, 32, 8) = 4096 blocks
    _DepthwiseFIRConv1d_kernel<<<grid, THREADS>>>(x, w, yv);
}

// round 5
// speedup vs baseline: 1.5878x; 1.0348x over previous
#include <cuda_runtime.h>
#include <cstdint>

// Depthwise causal FIR conv1d, K=31, fp32.
// x: (8, 4096, 2048) channel-last.  w: (2048, 31).  y like x.
//
// Round-5: cp.async-pipelined streaming register window (R4 with the ring
// race fixed: epilogue order is now wait -> consume -> issue, so at most
// RINGB=4 batches are in flight and a slot is rewritten only after its
// batch has been consumed).

#define BB 8
#define LL 4096
#define CP 1024          // channel pairs
#define KK 31
#define CHUNK 8
#define TT 128
#define NCHUNK 16
#define WBUF 38          // 30 halo + 8 current
#define THREADS 64
#define RINGB 4          // cp.async batches in flight

__device__ __forceinline__ float2 ffma2(float2 a, float2 b, float2 c) {
    float2 d;
    asm("fma.rn.f32x2 %0, %1, %2, %3;"
        : "=l"(*reinterpret_cast<unsigned long long*>(&d))
        : "l"(*reinterpret_cast<const unsigned long long*>(&a)),
          "l"(*reinterpret_cast<const unsigned long long*>(&b)),
          "l"(*reinterpret_cast<const unsigned long long*>(&c)));
    return d;
}

__device__ __forceinline__ void cp_async8(uint32_t saddr, const void* gptr) {
    asm volatile("cp.async.ca.shared.global [%0], [%1], 8;"
                 :: "r"(saddr), "l"(gptr) : "memory");
}
__device__ __forceinline__ void cp_commit() {
    asm volatile("cp.async.commit_group;" ::: "memory");
}
__device__ __forceinline__ void cp_wait3() {
    asm volatile("cp.async.wait_group 3;" ::: "memory");
}

__global__ __launch_bounds__(THREADS, 6)
void _DepthwiseFIRConv1d_kernel(const float* __restrict__ x,
                                const float* __restrict__ w,
                                float* __restrict__ y) {
    // ring[row][tid]: row = (batch & 3)*8 + i; per-thread column -> conflict-free
    __shared__ float2 ring[RINGB * CHUNK][THREADS];      // 16 KB

    const int tid = threadIdx.x;
    const int cp  = blockIdx.x * THREADS + tid;          // 0..1023
    const int l0  = blockIdx.y * TT;
    const int b   = blockIdx.z;

    const float2* xb = reinterpret_cast<const float2*>(x) + (size_t)b * LL * CP + cp;
    float2*       yb = reinterpret_cast<float2*>(y) + ((size_t)b * LL + l0) * CP + cp;
    const int base = l0 - (KK - 1);

    const uint32_t s0 = (uint32_t)__cvta_generic_to_shared(&ring[0][tid]);

    // Taps for both channels -> registers (reused for 128 outputs).
    const float* w0 = w + (2 * cp) * KK;
    float2 wt[KK];
#pragma unroll
    for (int t = 0; t < KK; t++)
        wt[t] = make_float2(__ldg(w0 + t), __ldg(w0 + KK + t));

    // Initial window: offsets 0..37 (chunk 0's span). Predicate only for l0==0.
    float2 buf[WBUF];
#pragma unroll
    for (int i = 0; i < WBUF; i++) {
        const int l = base + i;
        buf[i] = (l >= 0) ? xb[(size_t)l * CP] : make_float2(0.0f, 0.0f);
    }

    // Prologue: issue batches 1..4 (batch k = offsets 8k+30 .. 8k+37, consumed
    // at the END of chunk k-1 / start of chunk k). l = l0 + 8(k-1) + i, in-range.
#pragma unroll
    for (int k = 1; k <= RINGB; k++) {
#pragma unroll
        for (int i = 0; i < CHUNK; i++) {
            const int off = 8 * k + 30 + i;
            cp_async8(s0 + (uint32_t)(((k & 3) * CHUNK + i) * (THREADS * 8)),
                      xb + (size_t)(base + off) * CP);
        }
        cp_commit();
    }

#pragma unroll
    for (int c = 0; c < NCHUNK; c++) {
        float2 acc[CHUNK];
#pragma unroll
        for (int j = 0; j < CHUNK; j++) acc[j] = make_float2(0.0f, 0.0f);

#pragma unroll
        for (int t = 0; t < KK; t++) {
#pragma unroll
            for (int j = 0; j < CHUNK; j++) {
                acc[j] = ffma2(wt[t], buf[(CHUNK * c + j + t) % WBUF], acc[j]);
            }
        }

#pragma unroll
        for (int j = 0; j < CHUNK; j++)
            yb[(size_t)(CHUNK * c + j) * CP] = acc[j];

        if (c < NCHUNK - 1) {
            // 1) wait: oldest of the <=4 pending groups (batch c+1) completes
            cp_wait3();
            // 2) consume batch c+1: offsets 8c+38+i -> slot (8c+i) % 38 (just retired)
#pragma unroll
            for (int i = 0; i < CHUNK; i++)
                buf[(CHUNK * c + i) % WBUF] = ring[((c + 1) & 3) * CHUNK + i][tid];
            // 3) issue batch c+5 into the slot just consumed ((c+5)&3 == (c+1)&3)
            if (c + 5 <= NCHUNK - 1) {
#pragma unroll
                for (int i = 0; i < CHUNK; i++) {
                    const int k = c + 5;
                    const int off = 8 * k + 30 + i;
                    cp_async8(s0 + (uint32_t)(((k & 3) * CHUNK + i) * (THREADS * 8)),
                              xb + (size_t)(base + off) * CP);
                }
            }
            cp_commit();   // empty groups in the tail keep the count uniform
        }
    }
}

extern "C" void kernel_launch(void* const* d_in, const int* in_sizes, int n_in,
                              void* d_out, int out_size) {
    const float* x = (const float*)d_in[0];   // (8, 4096, 16, 128)
    const float* w = (const float*)d_in[1];   // (16, 128, 31)
    float* yv = (float*)d_out;

    dim3 grid(CP / THREADS, LL / TT, BB);     // (16, 32, 8) = 4096 blocks
    _DepthwiseFIRConv1d_kernel<<<grid, THREADS>>>(x, w, yv);
}